// round 17
// baseline (speedup 1.0000x reference)
#include <cuda_runtime.h>
#include <cstdint>

// Problem constants
#define B_    8
#define C_    512
#define N_    1024
#define HEADS 8
#define DH    64
#define GROUPS 32

// Scratch (allocation-free: device globals). All bf16 pair-packed as u32 words.
__device__ uint32_t g_h[(size_t)B_ * 1024 * 256];     // GN out, [n][kp]   (8 MB)
__device__ uint32_t g_qkvw[(size_t)B_ * 1536 * 512];  // v region used     (25 MB)
__device__ uint32_t g_qT[(size_t)B_ * 8 * 1024 * 32]; // q [b,h,i][d2]     (8 MB)
__device__ uint32_t g_kT[(size_t)B_ * 8 * 1024 * 32]; // k [b,h,i][d2]     (8 MB)
__device__ uint32_t g_aow[(size_t)B_ * 1024 * 256];   // attn out [n][kp]  (8 MB)
__device__ uint32_t g_wq[1536 * 256];                 // qkv_w bf16
__device__ uint32_t g_wp[512 * 256];                  // proj_w bf16

// ---------------------------------------------------------------------------
// helpers (plain sm_80+ PTX — safe for the sm_103 compile target)
// ---------------------------------------------------------------------------
__device__ __forceinline__ void mma_bf16(float* c, const uint32_t* a, const uint32_t* b) {
    asm("mma.sync.aligned.m16n8k16.row.col.f32.bf16.bf16.f32 "
        "{%0,%1,%2,%3}, {%4,%5,%6,%7}, {%8,%9}, {%0,%1,%2,%3};"
        : "+f"(c[0]), "+f"(c[1]), "+f"(c[2]), "+f"(c[3])
        : "r"(a[0]), "r"(a[1]), "r"(a[2]), "r"(a[3]), "r"(b[0]), "r"(b[1]));
}
__device__ __forceinline__ void ldsm4(uint32_t* r, uint32_t addr) {
    asm volatile("ldmatrix.sync.aligned.m8n8.x4.shared.b16 {%0,%1,%2,%3}, [%4];"
                 : "=r"(r[0]), "=r"(r[1]), "=r"(r[2]), "=r"(r[3]) : "r"(addr));
}
__device__ __forceinline__ uint32_t bf2(float lo, float hi) {   // word: lo16=lo
    uint32_t w;
    asm("cvt.rn.satfinite.bf16x2.f32 %0, %1, %2;" : "=r"(w) : "f"(hi), "f"(lo));
    return w;
}
__device__ __forceinline__ uint16_t bfh(float x) {
    uint16_t h;
    asm("cvt.rn.bf16.f32 %0, %1;" : "=h"(h) : "f"(x));
    return h;
}
__device__ __forceinline__ float ex2(float x) {
    float r;
    asm("ex2.approx.f32 %0, %1;" : "=f"(r) : "f"(x));
    return r;
}
__device__ __forceinline__ uint32_t smem_u32(const void* p) {
    uint32_t a;
    asm("{ .reg .u64 t; cvta.to.shared.u64 t, %1; cvt.u32.u64 %0, t; }"
        : "=r"(a) : "l"(p));
    return a;
}
__device__ __forceinline__ void cp16(uint32_t dst, const void* src) {
    asm volatile("cp.async.cg.shared.global [%0], [%1], 16;" :: "r"(dst), "l"(src));
}
#define CP_COMMIT() asm volatile("cp.async.commit_group;" ::: "memory")
#define CP_WAIT(n)  asm volatile("cp.async.wait_group %0;" :: "n"(n) : "memory")

// ---------------------------------------------------------------------------
// Weight conversion (both weights in one launch)
// ---------------------------------------------------------------------------
#define WQ4 (1536 * 128)
#define WP4 (512 * 128)
__global__ __launch_bounds__(256)
void wconv2(const float4* __restrict__ qw, const float4* __restrict__ pw,
            uint2* __restrict__ dq, uint2* __restrict__ dp) {
    int i = blockIdx.x * 256 + threadIdx.x;
    if (i < WQ4) {
        float4 v = qw[i];
        dq[i] = make_uint2(bf2(v.x, v.y), bf2(v.z, v.w));
    } else if (i - WQ4 < WP4) {
        float4 v = pw[i - WQ4];
        dp[i - WQ4] = make_uint2(bf2(v.x, v.y), bf2(v.z, v.w));
    }
}

// ---------------------------------------------------------------------------
// GroupNorm -> k-major pair words: g_h[(b*1024+n)*256 + kp]
// ---------------------------------------------------------------------------
__global__ __launch_bounds__(256)
void gn_kernel(const float* __restrict__ x, const float* __restrict__ w,
               const float* __restrict__ bb) {
    int bg = blockIdx.x;
    int b = bg >> 5, g = bg & 31;
    const float4* xp = (const float4*)(x + ((size_t)b * C_ + g * 16) * N_);

    float s = 0.f, s2 = 0.f;
    for (int idx = threadIdx.x; idx < 4096; idx += 256) {
        float4 v = xp[idx];
        s  += v.x + v.y + v.z + v.w;
        s2 += v.x * v.x + v.y * v.y + v.z * v.z + v.w * v.w;
    }
    #pragma unroll
    for (int off = 16; off; off >>= 1) {
        s  += __shfl_xor_sync(0xffffffffu, s, off);
        s2 += __shfl_xor_sync(0xffffffffu, s2, off);
    }
    __shared__ float sh[16];
    __shared__ float smu, srstd;
    int warp = threadIdx.x >> 5, lane = threadIdx.x & 31;
    if (lane == 0) { sh[warp] = s; sh[warp + 8] = s2; }
    __syncthreads();
    if (threadIdx.x == 0) {
        float ts = 0.f, ts2 = 0.f;
        #pragma unroll
        for (int i = 0; i < 8; i++) { ts += sh[i]; ts2 += sh[i + 8]; }
        float mu  = ts * (1.f / 16384.f);
        float var = ts2 * (1.f / 16384.f) - mu * mu;
        smu = mu;
        srstd = rsqrtf(var + 1e-5f);
    }
    __syncthreads();
    float mu = smu, rstd = srstd;

    int tid = threadIdx.x;
    float hv[16][4];
    #pragma unroll
    for (int cc = 0; cc < 16; cc++) {
        int c = g * 16 + cc;
        float sc = w[c] * rstd, tc = bb[c] - mu * sc;
        float4 v = ((const float4*)(x + ((size_t)b * C_ + c) * N_))[tid];
        hv[cc][0] = v.x * sc + tc; hv[cc][1] = v.y * sc + tc;
        hv[cc][2] = v.z * sc + tc; hv[cc][3] = v.w * sc + tc;
    }
    uint32_t* hw = g_h + (size_t)b * 1024 * 256 + g * 8;
    #pragma unroll
    for (int k = 0; k < 4; k++) {
        uint4 w0, w1;
        w0.x = bf2(hv[0][k],  hv[1][k]);  w0.y = bf2(hv[2][k],  hv[3][k]);
        w0.z = bf2(hv[4][k],  hv[5][k]);  w0.w = bf2(hv[6][k],  hv[7][k]);
        w1.x = bf2(hv[8][k],  hv[9][k]);  w1.y = bf2(hv[10][k], hv[11][k]);
        w1.z = bf2(hv[12][k], hv[13][k]); w1.w = bf2(hv[14][k], hv[15][k]);
        *(uint4*)(hw + (size_t)(4 * tid + k) * 256)     = w0;
        *(uint4*)(hw + (size_t)(4 * tid + k) * 256 + 4) = w1;
    }
}

// ---------------------------------------------------------------------------
// bf16 mma.sync GEMM: K-tile 64, 3-stage cp.async, ldmatrix both operands.
// RES=true : fp32 out + residual (proj).
// RES=false: qkv. v rows (blockIdx.y>=8) -> OutW [row][n/2]; q/k rows ->
//            transposed pair layout qT/kT[(b,h,i)][d2] via smem staging.
// ---------------------------------------------------------------------------
#define PA 36
#define STG_W (256 * PA)                      // 9216 words per stage
#define GM_SMEM (3 * STG_W * 4)               // 110,592 B

template <bool RES>
__global__ __launch_bounds__(256)
void tc_gemm(const uint32_t* __restrict__ A, const float* __restrict__ bias,
             const uint32_t* __restrict__ Bw, const float* __restrict__ X,
             float* __restrict__ OutF, uint32_t* __restrict__ OutW,
             uint32_t* __restrict__ qTo, uint32_t* __restrict__ kTo, int M) {
    extern __shared__ uint32_t smp[];

    int tid = threadIdx.x;
    int wid = tid >> 5, lane = tid & 31;
    int g = lane >> 2, tg = lane & 3;
    int warpM = wid >> 2, warpN = wid & 3;
    int wmRow = warpM * 64, wnCol = warpN * 32;

    int rowin = lane & 7, matid = lane >> 3;
    int lmRow = wmRow + (matid & 1) * 8 + rowin;
    int lmKp  = (matid >> 1) * 4;
    int bRow  = wnCol + (matid >> 1) * 8 + rowin;
    int bKp   = (matid & 1) * 4;

    int b = blockIdx.z;
    int n0 = blockIdx.x * 128, o0 = blockIdx.y * 128;
    const uint32_t* Bp = Bw + (size_t)b * 1024 * 256;

    uint32_t sbase = smem_u32(smp);

    auto load_tile = [&](int t, int s) {
        uint32_t as = sbase + (uint32_t)(s * STG_W) * 4u;
        uint32_t bs = as + 128u * PA * 4u;
        #pragma unroll
        for (int it = 0; it < 4; it++) {
            int idx = it * 256 + tid;
            int o = idx >> 3, ch = idx & 7;
            cp16(as + (uint32_t)(o * PA + ch * 4) * 4u,
                 A + (size_t)(o0 + o) * 256 + t * 32 + ch * 4);
        }
        #pragma unroll
        for (int it = 0; it < 4; it++) {
            int idx = it * 256 + tid;
            int r = idx >> 3, ch = idx & 7;
            cp16(bs + (uint32_t)(r * PA + ch * 4) * 4u,
                 Bp + (size_t)(n0 + r) * 256 + t * 32 + ch * 4);
        }
        CP_COMMIT();
    };

    float acc[4][4][4];
    #pragma unroll
    for (int mf = 0; mf < 4; mf++)
        #pragma unroll
        for (int nf = 0; nf < 4; nf++)
            #pragma unroll
            for (int i = 0; i < 4; i++) acc[mf][nf][i] = 0.f;

    load_tile(0, 0);
    load_tile(1, 1);

    for (int t = 0; t < 8; t++) {
        if (t < 7) { CP_WAIT(1); } else { CP_WAIT(0); }
        __syncthreads();
        if (t + 2 < 8) load_tile(t + 2, (t + 2) % 3);

        int s = t % 3;
        uint32_t aAddr = sbase + (uint32_t)(s * STG_W + lmRow * PA + lmKp) * 4u;
        uint32_t bAddr = sbase + (uint32_t)(s * STG_W + 128 * PA + bRow * PA + bKp) * 4u;

        #pragma unroll
        for (int ks = 0; ks < 4; ks++) {
            uint32_t a[4][4], bq[2][4];
            #pragma unroll
            for (int mf = 0; mf < 4; mf++)
                ldsm4(a[mf], aAddr + (uint32_t)(mf * 16 * PA + ks * 8) * 4u);
            #pragma unroll
            for (int np = 0; np < 2; np++)
                ldsm4(bq[np], bAddr + (uint32_t)(np * 16 * PA + ks * 8) * 4u);
            #pragma unroll
            for (int mf = 0; mf < 4; mf++)
                #pragma unroll
                for (int nf = 0; nf < 4; nf++)
                    mma_bf16(acc[mf][nf], a[mf], &bq[nf >> 1][(nf & 1) * 2]);
        }
    }

    if (RES) {
        #pragma unroll
        for (int mf = 0; mf < 4; mf++) {
            int r = o0 + wmRow + mf * 16 + g;
            float bi0 = bias[r], bi1 = bias[r + 8];
            size_t base0 = (size_t)b * M * N_ + (size_t)r * N_ + n0;
            size_t base1 = base0 + 8 * (size_t)N_;
            #pragma unroll
            for (int nf = 0; nf < 4; nf++) {
                int col = wnCol + nf * 8 + tg * 2;
                float2 v0 = make_float2(acc[mf][nf][0] + bi0, acc[mf][nf][1] + bi0);
                float2 v1 = make_float2(acc[mf][nf][2] + bi1, acc[mf][nf][3] + bi1);
                float2 x0 = *(const float2*)(X + base0 + col);
                float2 x1 = *(const float2*)(X + base1 + col);
                v0.x += x0.x; v0.y += x0.y;
                v1.x += x1.x; v1.y += x1.y;
                *(float2*)(OutF + base0 + col) = v0;
                *(float2*)(OutF + base1 + col) = v1;
            }
        }
    } else if (blockIdx.y >= 8) {
        // v rows: original [row][n/2] pair-along-n layout
        #pragma unroll
        for (int mf = 0; mf < 4; mf++) {
            int r = o0 + wmRow + mf * 16 + g;
            float bi0 = bias[r], bi1 = bias[r + 8];
            size_t w0 = ((size_t)b * 1536 + r) * 512;
            size_t w1 = w0 + 8 * 512;
            #pragma unroll
            for (int nf = 0; nf < 4; nf++) {
                int wc = ((n0 + wnCol + nf * 8) >> 1) + tg;
                OutW[w0 + wc] = bf2(acc[mf][nf][0] + bi0, acc[mf][nf][1] + bi0);
                OutW[w1 + wc] = bf2(acc[mf][nf][2] + bi1, acc[mf][nf][3] + bi1);
            }
        }
    } else {
        // q/k rows: transpose to [(b,h,i)][d2] pair-along-d via smem staging
        __syncthreads();               // stages free
        uint16_t* Eh = (uint16_t*)smp; // [128 n][130 bf16] = [n][65 words]
        #pragma unroll
        for (int mf = 0; mf < 4; mf++) {
            int rl = wmRow + mf * 16 + g;
            float bi0 = bias[o0 + rl], bi1 = bias[o0 + rl + 8];
            #pragma unroll
            for (int nf = 0; nf < 4; nf++) {
                int nl = wnCol + nf * 8 + tg * 2;
                Eh[nl * 130 + rl]           = bfh(acc[mf][nf][0] + bi0);
                Eh[(nl + 1) * 130 + rl]     = bfh(acc[mf][nf][1] + bi0);
                Eh[nl * 130 + rl + 8]       = bfh(acc[mf][nf][2] + bi1);
                Eh[(nl + 1) * 130 + rl + 8] = bfh(acc[mf][nf][3] + bi1);
            }
        }
        __syncthreads();
        int qk = blockIdx.y >> 2;                 // 0=q, 1=k
        uint32_t* gT = qk ? kTo : qTo;
        int h0 = (o0 - qk * 512) >> 6;            // 2 heads per tile
        #pragma unroll
        for (int it = 0; it < 32; it++) {
            int idx = it * 256 + tid;
            int i = idx >> 6, w = idx & 63;
            int h = h0 + (w >> 5);
            gT[(((size_t)b * 8 + h) * 1024 + n0 + i) * 32 + (w & 31)] =
                smp[i * 65 + w];
        }
    }
}

// ---------------------------------------------------------------------------
// bf16 mma.sync flash attention. Q/K tiles: straight cp.async from qT/kT
// ([i][d2] pair words, pitch 36) + dual-ldsm4 S-MMA (GEMM recipe). K double-
// buffered; V single-buffered with post-softmax wait (proven). 2 barriers/tile.
// ---------------------------------------------------------------------------
#define QS_W  (128 * 36)                      // 4608
#define KS_OFF QS_W                           // 2 stages of 4608
#define VS_OFF (QS_W * 3)                     // 13824
#define PS_OFF (VS_OFF + 64 * 68)             // 18176
#define ATT_SMEM ((PS_OFF + 128 * 68) * 4)    // 107,520 B
#define K8 0.18033688011112042f               // 0.125 * log2(e)

__global__ __launch_bounds__(256, 2)
void attn_tc(const uint32_t* __restrict__ qT, const uint32_t* __restrict__ kT,
             const uint32_t* __restrict__ qkvw, uint32_t* __restrict__ aow) {
    extern __shared__ uint32_t smw[];
    uint32_t* Ps = smw + PS_OFF;

    int bh = blockIdx.y;
    int b = bh >> 3, h = bh & 7;
    int i0 = blockIdx.x * 128;
    const uint32_t* qTb = qT + (size_t)(b * 8 + h) * 1024 * 32;
    const uint32_t* kTb = kT + (size_t)(b * 8 + h) * 1024 * 32;
    const uint32_t* vb  = qkvw + ((size_t)b * 1536 + 1024 + h * 64) * 512;

    int tid = threadIdx.x;
    int wid = tid >> 5, lane = tid & 31;
    int g = lane >> 2, tg = lane & 3;
    int rowin = lane & 7, matid = lane >> 3;
    int r0 = wid * 16;
    uint32_t* Psw = Ps + r0 * 68;

    uint32_t sb = smem_u32(smw);
    uint32_t qAddr  = sb + (uint32_t)(((r0 + (matid & 1) * 8 + rowin) * 36
                                      + (matid >> 1) * 4) * 4);
    uint32_t kFrag  = (uint32_t)((((matid >> 1) * 8 + rowin) * 36
                                  + (matid & 1) * 4) * 4);
    uint32_t vsBase = sb + (uint32_t)(VS_OFF * 4)
        + (uint32_t)((((matid >> 1) * 8 + rowin) * 68 + (matid & 1) * 4) * 4);

    // prologue: Q tile + K tile 0 (stage 0)
    #pragma unroll
    for (int it = 0; it < 4; it++) {
        int idx = it * 256 + tid;
        int row = idx >> 3, ch = idx & 7;
        cp16(sb + (uint32_t)((row * 36 + ch * 4) * 4),
             qTb + (size_t)(i0 + row) * 32 + ch * 4);
        cp16(sb + (uint32_t)((KS_OFF + row * 36 + ch * 4) * 4),
             kTb + (size_t)row * 32 + ch * 4);
    }
    CP_COMMIT();
    CP_WAIT(0);
    __syncthreads();

    float m0 = -1e30f, m1 = -1e30f, l0 = 0.f, l1 = 0.f;
    float o_acc[8][4];
    #pragma unroll
    for (int nf = 0; nf < 8; nf++)
        #pragma unroll
        for (int i = 0; i < 4; i++) o_acc[nf][i] = 0.f;

    int cpD = tid >> 2, cpC = tid & 3;

    for (int t = 0; t < 8; t++) {
        int j0 = t * 128;
        if (t) __syncthreads();       // all warps done with Vs (PV t-1)

        // issue V(t); prefetch K(t+1) into the other stage
        #pragma unroll
        for (int it = 0; it < 4; it++)
            cp16(sb + (uint32_t)((VS_OFF + cpD * 68 + cpC * 4 + it * 16) * 4),
                 vb + (size_t)cpD * 512 + (j0 >> 1) + cpC * 4 + it * 16);
        if (t < 7) {
            uint32_t ksDst = sb + (uint32_t)((KS_OFF + ((t + 1) & 1) * QS_W) * 4);
            #pragma unroll
            for (int it = 0; it < 4; it++) {
                int idx = it * 256 + tid;
                int row = idx >> 3, ch = idx & 7;
                cp16(ksDst + (uint32_t)((row * 36 + ch * 4) * 4),
                     kTb + (size_t)(j0 + 128 + row) * 32 + ch * 4);
            }
        }
        CP_COMMIT();

        // S = Q K^T (dual ldsm4, GEMM recipe)
        uint32_t ksCur = sb + (uint32_t)((KS_OFF + (t & 1) * QS_W) * 4) + kFrag;
        float acc[16][4];
        #pragma unroll
        for (int nf = 0; nf < 16; nf++)
            #pragma unroll
            for (int i = 0; i < 4; i++) acc[nf][i] = 0.f;

        #pragma unroll
        for (int ks = 0; ks < 4; ks++) {
            uint32_t a[4];
            ldsm4(a, qAddr + (uint32_t)(ks * 8 * 4));
            #pragma unroll
            for (int nb = 0; nb < 8; nb++) {
                uint32_t bq[4];
                ldsm4(bq, ksCur + (uint32_t)((nb * 16 * 36 + ks * 8) * 4));
                mma_bf16(acc[nb * 2],     a, &bq[0]);
                mma_bf16(acc[nb * 2 + 1], a, &bq[2]);
            }
        }

        // online softmax (1/8 scale folded into exp2 constant)
        float rm0 = -1e30f, rm1 = -1e30f;
        #pragma unroll
        for (int nf = 0; nf < 16; nf++) {
            rm0 = fmaxf(rm0, fmaxf(acc[nf][0], acc[nf][1]));
            rm1 = fmaxf(rm1, fmaxf(acc[nf][2], acc[nf][3]));
        }
        rm0 = fmaxf(rm0, __shfl_xor_sync(0xffffffffu, rm0, 1));
        rm0 = fmaxf(rm0, __shfl_xor_sync(0xffffffffu, rm0, 2));
        rm1 = fmaxf(rm1, __shfl_xor_sync(0xffffffffu, rm1, 1));
        rm1 = fmaxf(rm1, __shfl_xor_sync(0xffffffffu, rm1, 2));
        float mn0 = fmaxf(m0, rm0), mn1 = fmaxf(m1, rm1);
        float c0 = ex2((m0 - mn0) * K8), c1 = ex2((m1 - mn1) * K8);
        l0 *= c0; l1 *= c1;
        #pragma unroll
        for (int nf = 0; nf < 8; nf++) {
            o_acc[nf][0] *= c0; o_acc[nf][1] *= c0;
            o_acc[nf][2] *= c1; o_acc[nf][3] *= c1;
        }
        float s0 = 0.f, s1 = 0.f;
        #pragma unroll
        for (int nf = 0; nf < 16; nf++) {
            float p0 = ex2((acc[nf][0] - mn0) * K8);
            float p1 = ex2((acc[nf][1] - mn0) * K8);
            float p2 = ex2((acc[nf][2] - mn1) * K8);
            float p3 = ex2((acc[nf][3] - mn1) * K8);
            s0 += p0 + p1; s1 += p2 + p3;
            Psw[g * 68 + nf * 4 + tg]       = bf2(p0, p1);
            Psw[(g + 8) * 68 + nf * 4 + tg] = bf2(p2, p3);
        }
        s0 += __shfl_xor_sync(0xffffffffu, s0, 1);
        s0 += __shfl_xor_sync(0xffffffffu, s0, 2);
        s1 += __shfl_xor_sync(0xffffffffu, s1, 1);
        s1 += __shfl_xor_sync(0xffffffffu, s1, 2);
        l0 += s0; l1 += s1; m0 = mn0; m1 = mn1;

        CP_WAIT(0);
        __syncthreads();   // V(t) and K(t+1) visible; Psw visible in-warp

        // O += P @ V^T
        #pragma unroll
        for (int kk = 0; kk < 8; kk++) {
            int jp = kk * 8;
            uint32_t a[4];
            a[0] = Psw[g * 68 + jp + tg];
            a[1] = Psw[(g + 8) * 68 + jp + tg];
            a[2] = Psw[g * 68 + jp + tg + 4];
            a[3] = Psw[(g + 8) * 68 + jp + tg + 4];
            uint32_t bq[4][4];
            #pragma unroll
            for (int q = 0; q < 4; q++)
                ldsm4(bq[q], vsBase + (uint32_t)((q * 16 * 68 + jp) * 4));
            #pragma unroll
            for (int nf = 0; nf < 8; nf++)
                mma_bf16(o_acc[nf], a, &bq[nf >> 1][(nf & 1) * 2]);
        }
    }

    // epilogue: normalize -> Os[128 i][33] (reuse Ps) -> coalesced k-major store
    __syncthreads();
    float inv0 = 1.f / l0, inv1 = 1.f / l1;
    uint32_t* Os = Ps;
    #pragma unroll
    for (int nf = 0; nf < 8; nf++) {
        int d2 = nf * 4 + tg;
        Os[(r0 + g) * 33 + d2]     = bf2(o_acc[nf][0] * inv0, o_acc[nf][1] * inv0);
        Os[(r0 + g + 8) * 33 + d2] = bf2(o_acc[nf][2] * inv1, o_acc[nf][3] * inv1);
    }
    __syncthreads();
    uint32_t* aob = aow + (size_t)b * 1024 * 256 + h * 32;
    #pragma unroll
    for (int it = 0; it < 16; it++) {
        int idx = it * 256 + tid;
        int i = idx >> 5, c2 = idx & 31;
        aob[(size_t)(i0 + i) * 256 + c2] = Os[i * 33 + c2];
    }
}

// ---------------------------------------------------------------------------
extern "C" void kernel_launch(void* const* d_in, const int* in_sizes, int n_in,
                              void* d_out, int out_size) {
    const float* x      = (const float*)d_in[0];
    const float* gn_w   = (const float*)d_in[1];
    const float* gn_b   = (const float*)d_in[2];
    const float* qkv_w  = (const float*)d_in[3];
    const float* qkv_b  = (const float*)d_in[4];
    const float* proj_w = (const float*)d_in[5];
    const float* proj_b = (const float*)d_in[6];
    float* out = (float*)d_out;

    uint32_t *hbuf, *qkvbuf, *aobuf, *wq, *wp, *qTbuf, *kTbuf;
    cudaGetSymbolAddress((void**)&hbuf,   g_h);
    cudaGetSymbolAddress((void**)&qkvbuf, g_qkvw);
    cudaGetSymbolAddress((void**)&aobuf,  g_aow);
    cudaGetSymbolAddress((void**)&wq,     g_wq);
    cudaGetSymbolAddress((void**)&wp,     g_wp);
    cudaGetSymbolAddress((void**)&qTbuf,  g_qT);
    cudaGetSymbolAddress((void**)&kTbuf,  g_kT);

    cudaFuncSetAttribute(attn_tc, cudaFuncAttributeMaxDynamicSharedMemorySize, ATT_SMEM);
    cudaFuncSetAttribute(tc_gemm<false>, cudaFuncAttributeMaxDynamicSharedMemorySize, GM_SMEM);
    cudaFuncSetAttribute(tc_gemm<true>,  cudaFuncAttributeMaxDynamicSharedMemorySize, GM_SMEM);

    // 0) weight conversion (both, one launch)
    wconv2<<<(WQ4 + WP4 + 255) / 256, 256>>>((const float4*)qkv_w, (const float4*)proj_w,
                                             (uint2*)wq, (uint2*)wp);
    // 1) GroupNorm -> k-major bf16 pair words
    gn_kernel<<<B_ * GROUPS, 256>>>(x, gn_w, gn_b);
    // 2) QKV GEMM: q/k -> transposed [i][d2]; v -> [row][n/2]
    tc_gemm<false><<<dim3(8, 12, B_), 256, GM_SMEM>>>(wq, qkv_b, hbuf, nullptr,
                                                      nullptr, qkvbuf, qTbuf, kTbuf, 1536);
    // 3) Flash attention (dual-ldsm4 S-MMA, async Q/K/V)
    attn_tc<<<dim3(8, B_ * HEADS), 256, ATT_SMEM>>>(qTbuf, kTbuf, qkvbuf, aobuf);
    // 4) Proj GEMM + bias + residual -> fp32 out
    tc_gemm<true><<<dim3(8, 4, B_), 256, GM_SMEM>>>(wp, proj_b, aobuf, x,
                                                    out, nullptr, nullptr, nullptr, 512);
}